// round 1
// baseline (speedup 1.0000x reference)
#include <cuda_runtime.h>
#include <cstdint>

#define NMAX 100000
#define HD   128
#define BMAX 256
#define OMAX 32

// ---------------- static scratch (no allocations allowed) ----------------
__device__ float    g_h   [NMAX * HD];
__device__ float    g_agg [NMAX * HD];
__device__ float    g_z1  [NMAX * HD];
__device__ float    g_stats[2 * HD];
__device__ float    g_ssum[BMAX * HD];
__device__ unsigned g_smax[BMAX * HD];
__device__ int      g_cnt [BMAX];
__device__ float    g_graph[BMAX * 384];
__device__ float    g_oe  [BMAX * OMAX * HD];
__device__ float    g_comb[BMAX * OMAX * 512];
__device__ float    g_s1  [BMAX * OMAX * HD];
__device__ float    g_s2  [BMAX * OMAX * 64];

// order-preserving float<->uint encoding for atomic max (handles negatives, -0)
__device__ __forceinline__ unsigned fenc(float f) {
    unsigned u = __float_as_uint(f);
    return (u & 0x80000000u) ? ~u : (u | 0x80000000u);
}
__device__ __forceinline__ float fdec(unsigned u) {
    unsigned b = (u & 0x80000000u) ? (u & 0x7FFFFFFFu) : ~u;
    return __uint_as_float(b);
}
#define NEG_INF __uint_as_float(0xff800000u)

// ---------------- init: h = x, agg = x ----------------
__global__ void init_copy_k(const float* __restrict__ x, float* __restrict__ h,
                            float* __restrict__ agg, int total4) {
    int i = blockIdx.x * blockDim.x + threadIdx.x;
    if (i < total4) {
        float4 v = ((const float4*)x)[i];
        ((float4*)h)[i] = v;
        ((float4*)agg)[i] = v;
    }
}

// ---------------- edge scatter: agg[dst] += h[src]  (warp per edge) ----------------
__global__ void scatter_k(const float* __restrict__ h, float* __restrict__ agg,
                          const int* __restrict__ ei, int E) {
    int warp = blockIdx.x * (blockDim.x >> 5) + (threadIdx.x >> 5);
    int lane = threadIdx.x & 31;
    if (warp >= E) return;
    int s = __ldg(ei + warp);
    int d = __ldg(ei + E + warp);
    float4 v = __ldg((const float4*)(h + (size_t)s * HD) + lane);
    float* dp = agg + (size_t)d * HD + lane * 4;
    asm volatile("red.global.add.v4.f32 [%0], {%1,%2,%3,%4};"
                 :: "l"(dp), "f"(v.x), "f"(v.y), "f"(v.z), "f"(v.w) : "memory");
}

// ---------------- zero BN stats ----------------
__global__ void zero_k(float* s) { s[threadIdx.x] = 0.f; }

// ---------------- generic tiled GEMM: out[M,NT] = act(A[M,K] @ W[K,NT] + bias) ----------------
// block tile 128 x NT, thread micro-tile 8x8, THREADS = 2*NT (256 for NT=128, 128 for NT=64)
template <int NT, bool RELU, bool STATS>
__global__ __launch_bounds__(2 * NT, 2)
void gemm_k(const float* __restrict__ A, const float* __restrict__ W,
            const float* __restrict__ bias, float* __restrict__ out,
            int M, int K, float* __restrict__ stats) {
    constexpr int THREADS = 2 * NT;
    constexpr int TX = NT / 8;
    __shared__ float As[32][128];
    __shared__ float Bs[32][NT];
    const int tid = threadIdx.x;
    const int tx = tid % TX;
    const int ty = tid / TX;          // 0..15
    const int rowBase = blockIdx.x * 128;

    float acc[8][8];
#pragma unroll
    for (int j = 0; j < 8; j++)
#pragma unroll
        for (int i = 0; i < 8; i++) acc[j][i] = 0.f;

    for (int kt = 0; kt < K; kt += 32) {
        // A tile (transposed to As[k][row])
#pragma unroll
        for (int q0 = 0; q0 < 1024 / THREADS; q0++) {
            int q = q0 * THREADS + tid;
            int r = q >> 3;
            int kq = (q & 7) * 4;
            float4 v = make_float4(0.f, 0.f, 0.f, 0.f);
            int gr = rowBase + r;
            if (gr < M) v = *(const float4*)(A + (size_t)gr * K + kt + kq);
            As[kq + 0][r] = v.x; As[kq + 1][r] = v.y;
            As[kq + 2][r] = v.z; As[kq + 3][r] = v.w;
        }
        // W tile
#pragma unroll
        for (int q0 = 0; q0 < (32 * NT / 4) / THREADS; q0++) {
            int q = q0 * THREADS + tid;
            int kl = q / (NT / 4);
            int c4 = (q % (NT / 4)) * 4;
            *(float4*)&Bs[kl][c4] = *(const float4*)(W + (size_t)(kt + kl) * NT + c4);
        }
        __syncthreads();
#pragma unroll
        for (int kl = 0; kl < 32; kl++) {
            float a[8], b[8];
            *(float4*)&a[0] = *(const float4*)&As[kl][ty * 8];
            *(float4*)&a[4] = *(const float4*)&As[kl][ty * 8 + 4];
            *(float4*)&b[0] = *(const float4*)&Bs[kl][tx * 8];
            *(float4*)&b[4] = *(const float4*)&Bs[kl][tx * 8 + 4];
#pragma unroll
            for (int j = 0; j < 8; j++)
#pragma unroll
                for (int i = 0; i < 8; i++)
                    acc[j][i] = fmaf(a[j], b[i], acc[j][i]);
        }
        __syncthreads();
    }

    float br[8];
#pragma unroll
    for (int i = 0; i < 8; i++) br[i] = __ldg(bias + tx * 8 + i);

    float psum[8], psq[8];
#pragma unroll
    for (int i = 0; i < 8; i++) { psum[i] = 0.f; psq[i] = 0.f; }

#pragma unroll
    for (int j = 0; j < 8; j++) {
        int gr = rowBase + ty * 8 + j;
        if (gr >= M) continue;
        float v[8];
#pragma unroll
        for (int i = 0; i < 8; i++) {
            v[i] = acc[j][i] + br[i];
            if (RELU) v[i] = fmaxf(v[i], 0.f);
        }
        if (STATS) {
#pragma unroll
            for (int i = 0; i < 8; i++) { psum[i] += v[i]; psq[i] += v[i] * v[i]; }
        }
        float* op = out + (size_t)gr * NT + tx * 8;
        *(float4*)op       = make_float4(v[0], v[1], v[2], v[3]);
        *(float4*)(op + 4) = make_float4(v[4], v[5], v[6], v[7]);
    }

    if constexpr (STATS) {
        __shared__ float sp[16][128];
#pragma unroll
        for (int i = 0; i < 8; i++) sp[ty][tx * 8 + i] = psum[i];
        __syncthreads();
        if (tid < 128) {
            float s = 0.f;
#pragma unroll
            for (int k = 0; k < 16; k++) s += sp[k][tid];
            atomicAdd(&stats[tid], s);
        }
        __syncthreads();
#pragma unroll
        for (int i = 0; i < 8; i++) sp[ty][tx * 8 + i] = psq[i];
        __syncthreads();
        if (tid < 128) {
            float s = 0.f;
#pragma unroll
            for (int k = 0; k < 16; k++) s += sp[k][tid];
            atomicAdd(&stats[128 + tid], s);
        }
    }
}

// ---------------- BN apply (+optional relu), writes h and (optionally) agg ----------------
__global__ void bn_apply_k(const float* __restrict__ z, const float* __restrict__ stats,
                           const float* __restrict__ gamma, const float* __restrict__ beta,
                           float* __restrict__ h, float* __restrict__ agg,
                           int n, int doRelu, int doAgg, float invN) {
    __shared__ float sc[128], sh[128];
    if (threadIdx.x < 128) {
        float mu = stats[threadIdx.x] * invN;
        float q  = stats[128 + threadIdx.x] * invN;
        float var = q - mu * mu;
        float is = rsqrtf(var + 1e-5f);
        float s = is * gamma[threadIdx.x];
        sc[threadIdx.x] = s;
        sh[threadIdx.x] = beta[threadIdx.x] - mu * s;
    }
    __syncthreads();
    int total = n * 32;
    for (int i = blockIdx.x * blockDim.x + threadIdx.x; i < total;
         i += gridDim.x * blockDim.x) {
        int c = (i & 31) * 4;
        float4 v = ((const float4*)z)[i];
        float4 r;
        r.x = v.x * sc[c + 0] + sh[c + 0];
        r.y = v.y * sc[c + 1] + sh[c + 1];
        r.z = v.z * sc[c + 2] + sh[c + 2];
        r.w = v.w * sc[c + 3] + sh[c + 3];
        if (doRelu) {
            r.x = fmaxf(r.x, 0.f); r.y = fmaxf(r.y, 0.f);
            r.z = fmaxf(r.z, 0.f); r.w = fmaxf(r.w, 0.f);
        }
        ((float4*)h)[i] = r;
        if (doAgg) ((float4*)agg)[i] = r;
    }
}

// ---------------- pooling init ----------------
__global__ void pool_init_k(int B) {
    int i = blockIdx.x * blockDim.x + threadIdx.x;
    if (i < B * HD) { g_ssum[i] = 0.f; g_smax[i] = 0x007FFFFFu; /* enc(-inf) */ }
    if (i < B) g_cnt[i] = 0;
}

// ---------------- segment pooling (batch is sorted) ----------------
__global__ void pool_k(const float* __restrict__ h, const int* __restrict__ batch, int n) {
    const int t = threadIdx.x;               // 128 threads, one per feature
    int start = blockIdx.x * 256;
    int end = min(start + 256, n);
    if (start >= end) return;
    int cur = __ldg(batch + start);
    float s = 0.f, m = NEG_INF;
    int c = 0;
    for (int v0 = start; v0 < end; v0 += 8) {
        float vals[8]; int bs[8];
        int mm = min(8, end - v0);
#pragma unroll
        for (int k = 0; k < 8; k++) {
            if (k < mm) {
                vals[k] = __ldg(h + (size_t)(v0 + k) * HD + t);
                bs[k] = __ldg(batch + v0 + k);
            }
        }
        for (int k = 0; k < mm; k++) {
            if (bs[k] != cur) {
                atomicAdd(&g_ssum[cur * HD + t], s);
                atomicMax(&g_smax[cur * HD + t], fenc(m));
                if (t == 0) atomicAdd(&g_cnt[cur], c);
                cur = bs[k]; s = 0.f; m = NEG_INF; c = 0;
            }
            s += vals[k];
            m = fmaxf(m, vals[k]);
            c++;
        }
    }
    atomicAdd(&g_ssum[cur * HD + t], s);
    atomicMax(&g_smax[cur * HD + t], fenc(m));
    if (t == 0) atomicAdd(&g_cnt[cur], c);
}

// ---------------- graph feature build [mean | max | sum] ----------------
__global__ void graph_k(int B) {
    int i = blockIdx.x * blockDim.x + threadIdx.x;
    if (i >= B * 384) return;
    int b = i / 384, c = i % 384;
    float o;
    if (c < 128) {
        float cf = (float)max(g_cnt[b], 1);
        o = g_ssum[b * HD + c] / cf;
    } else if (c < 256) {
        int cc = c - 128;
        o = (g_cnt[b] == 0) ? 0.f : fdec(g_smax[b * HD + cc]);
    } else {
        o = g_ssum[b * HD + (c - 256)];
    }
    g_graph[i] = o;
}

// ---------------- comb = [graph(384) | oe(128)] ----------------
__global__ void comb_k(int rows) {
    int i = blockIdx.x * blockDim.x + threadIdx.x;   // float4 index
    int total = rows * 128;
    if (i >= total) return;
    int r = i >> 7, c4 = i & 127;
    float4 v;
    if (c4 < 96) v = *(const float4*)&g_graph[(r >> 5) * 384 + c4 * 4];
    else         v = *(const float4*)&g_oe[(size_t)r * HD + (c4 - 96) * 4];
    ((float4*)g_comb)[i] = v;
}

// ---------------- final dot: out[r] = s2[r,:] . sW3 + sb3 ----------------
__global__ void s3_k(const float* __restrict__ s2, const float* __restrict__ W,
                     const float* __restrict__ b, float* __restrict__ out, int rows) {
    int warp = (blockIdx.x * blockDim.x + threadIdx.x) >> 5;
    int lane = threadIdx.x & 31;
    if (warp >= rows) return;
    const float* row = s2 + (size_t)warp * 64;
    float s = row[lane] * W[lane] + row[lane + 32] * W[lane + 32];
#pragma unroll
    for (int o = 16; o > 0; o >>= 1) s += __shfl_down_sync(0xffffffffu, s, o);
    if (lane == 0) out[warp] = s + b[0];
}

// ---------------- launch ----------------
extern "C" void kernel_launch(void* const* d_in, const int* in_sizes, int n_in,
                              void* d_out, int out_size) {
    const float* x      = (const float*)d_in[0];
    const int*   ei     = (const int*)d_in[1];
    const float* orders = (const float*)d_in[2];
    const int*   batch  = (const int*)d_in[3];
    const float* gW1    = (const float*)d_in[4];
    const float* gb1    = (const float*)d_in[5];
    const float* gW2    = (const float*)d_in[6];
    const float* gb2    = (const float*)d_in[7];
    const float* gamma  = (const float*)d_in[8];
    const float* beta   = (const float*)d_in[9];
    const float* oW1    = (const float*)d_in[10];
    const float* ob1    = (const float*)d_in[11];
    const float* oW2    = (const float*)d_in[12];
    const float* ob2    = (const float*)d_in[13];
    const float* sW1    = (const float*)d_in[14];
    const float* sb1    = (const float*)d_in[15];
    const float* sW2    = (const float*)d_in[16];
    const float* sb2    = (const float*)d_in[17];
    const float* sW3    = (const float*)d_in[18];
    const float* sb3    = (const float*)d_in[19];
    float* out = (float*)d_out;

    const int n = in_sizes[0] / HD;
    const int E = in_sizes[1] / 2;
    const int B = in_sizes[2] / (OMAX * 32);
    const int L = in_sizes[4] / (HD * HD);
    const int rows = B * OMAX;

    float *hB, *aggB, *z1B, *statsB, *oeB, *combB, *s1B, *s2B;
    cudaGetSymbolAddress((void**)&hB, g_h);
    cudaGetSymbolAddress((void**)&aggB, g_agg);
    cudaGetSymbolAddress((void**)&z1B, g_z1);
    cudaGetSymbolAddress((void**)&statsB, g_stats);
    cudaGetSymbolAddress((void**)&oeB, g_oe);
    cudaGetSymbolAddress((void**)&combB, g_comb);
    cudaGetSymbolAddress((void**)&s1B, g_s1);
    cudaGetSymbolAddress((void**)&s2B, g_s2);

    const int f4n = n * 32;
    init_copy_k<<<(f4n + 255) / 256, 256>>>(x, hB, aggB, f4n);

    for (int l = 0; l < L; l++) {
        scatter_k<<<(E + 7) / 8, 256>>>(hB, aggB, ei, E);
        gemm_k<128, true, false><<<(n + 127) / 128, 256>>>(
            aggB, gW1 + (size_t)l * HD * HD, gb1 + l * HD, z1B, n, HD, nullptr);
        zero_k<<<1, 256>>>(statsB);
        gemm_k<128, false, true><<<(n + 127) / 128, 256>>>(
            z1B, gW2 + (size_t)l * HD * HD, gb2 + l * HD, aggB, n, HD, statsB);
        int last = (l == L - 1);
        bn_apply_k<<<4096, 256>>>(aggB, statsB, gamma + l * HD, beta + l * HD,
                                  hB, aggB, n, !last, !last, 1.0f / (float)n);
    }

    pool_init_k<<<(B * HD + 255) / 256, 256>>>(B);
    pool_k<<<(n + 255) / 256, 128>>>(hB, batch, n);
    graph_k<<<(B * 384 + 255) / 256, 256>>>(B);

    // order encoder: oe = relu(orders@oW1+ob1)@oW2+ob2
    gemm_k<128, true, false><<<(rows + 127) / 128, 256>>>(
        orders, oW1, ob1, z1B, rows, 32, nullptr);
    gemm_k<128, false, false><<<(rows + 127) / 128, 256>>>(
        z1B, oW2, ob2, oeB, rows, HD, nullptr);

    comb_k<<<(rows * 128 + 255) / 256, 256>>>(rows);

    // score head
    gemm_k<128, true, false><<<(rows + 127) / 128, 256>>>(
        combB, sW1, sb1, s1B, rows, 512, nullptr);
    gemm_k<64, true, false><<<(rows + 127) / 128, 128>>>(
        s1B, sW2, sb2, s2B, rows, HD, nullptr);
    s3_k<<<(rows + 7) / 8, 256>>>(s2B, sW3, sb3, out, rows);
}

// round 3
// speedup vs baseline: 1.1330x; 1.1330x over previous
#include <cuda_runtime.h>
#include <cuda_bf16.h>
#include <cstdint>

#define NMAX 100000
#define HD   128
#define BMAX 256
#define OMAX 32

// ---------------- static scratch ----------------
__device__ float    g_h   [NMAX * HD];
__device__ float    g_agg [NMAX * HD];
__device__ float    g_z1  [NMAX * HD];
__device__ float    g_stats[2 * HD];
__device__ float    g_ssum[BMAX * HD];
__device__ unsigned g_smax[BMAX * HD];
__device__ int      g_cnt [BMAX];
__device__ float    g_graph[BMAX * 384];
__device__ float    g_oe  [BMAX * OMAX * HD];
__device__ float    g_comb[BMAX * OMAX * 512];
__device__ float    g_s1  [BMAX * OMAX * HD];
__device__ float    g_s2  [BMAX * OMAX * 64];
__device__ __nv_bfloat16 g_wbf[368640];   // hi/lo split, transposed weights

__device__ __forceinline__ uint32_t smem_to_u32(const void* p) {
    uint32_t a;
    asm("{ .reg .u64 t; cvta.to.shared.u64 t, %1; cvt.u32.u64 %0, t; }" : "=r"(a) : "l"(p));
    return a;
}

// mma.sync bf16 m16n8k16 (baseline PTX, works on sm_100 plain)
#define MMA_BF16(c, a, b0, b1) \
    asm volatile("mma.sync.aligned.m16n8k16.row.col.f32.bf16.bf16.f32 " \
        "{%0,%1,%2,%3}, {%4,%5,%6,%7}, {%8,%9}, {%0,%1,%2,%3};" \
        : "+f"((c)[0]), "+f"((c)[1]), "+f"((c)[2]), "+f"((c)[3]) \
        : "r"((a)[0]), "r"((a)[1]), "r"((a)[2]), "r"((a)[3]), "r"(b0), "r"(b1))

#define LDSM4(r0, r1, r2, r3, addr) \
    asm volatile("ldmatrix.sync.aligned.m8n8.x4.shared.b16 {%0,%1,%2,%3}, [%4];" \
        : "=r"(r0), "=r"(r1), "=r"(r2), "=r"(r3) : "r"(addr))

__device__ __forceinline__ void cvt_hilo(float2 v, uint32_t& hi, uint32_t& lo) {
    __nv_bfloat162 h = __float22bfloat162_rn(v);
    float hx = __bfloat162float(h.x), hy = __bfloat162float(h.y);
    __nv_bfloat162 l = __float22bfloat162_rn(make_float2(v.x - hx, v.y - hy));
    hi = *(uint32_t*)&h;
    lo = *(uint32_t*)&l;
}

// float -> order-preserving uint (for atomic max)
__device__ __forceinline__ unsigned fenc(float f) {
    unsigned u = __float_as_uint(f);
    return (u & 0x80000000u) ? ~u : (u | 0x80000000u);
}
__device__ __forceinline__ float fdec(unsigned u) {
    unsigned b = (u & 0x80000000u) ? (u & 0x7FFFFFFFu) : ~u;
    return __uint_as_float(b);
}
#define NEG_INF __uint_as_float(0xff800000u)

// ---------------- weight prep: W[K,128] fp32 -> Wt_hi[N,K], Wt_lo[N,K] bf16 ----------------
__global__ void prep_k(const float* __restrict__ gW1, const float* __restrict__ gW2,
                       const float* __restrict__ oW1f, const float* __restrict__ oW2f,
                       const float* __restrict__ sW1f) {
    int idx = blockIdx.x * blockDim.x + threadIdx.x;
    if (idx >= 184320) return;
    const float* W; int K; int el; size_t hiB;
    if (idx < 98304) {
        int m = idx / 16384; el = idx % 16384; K = 128;
        W = (m < 3) ? gW1 + (size_t)m * 16384 : gW2 + (size_t)(m - 3) * 16384;
        hiB = (size_t)m * 32768;
    } else if (idx < 102400) { el = idx - 98304;  K = 32;  W = oW1f; hiB = 196608; }
    else if   (idx < 118784) { el = idx - 102400; K = 128; W = oW2f; hiB = 204800; }
    else                     { el = idx - 118784; K = 512; W = sW1f; hiB = 237568; }
    int nn = el / K, k = el % K;
    float v = W[(size_t)k * 128 + nn];
    __nv_bfloat16 h = __float2bfloat16(v);
    g_wbf[hiB + el] = h;
    g_wbf[hiB + (size_t)128 * K + el] = __float2bfloat16(v - __bfloat162float(h));
}

// ---------------- init ----------------
__global__ void init_copy_k(const float* __restrict__ x, float* __restrict__ h,
                            float* __restrict__ agg, int total4) {
    int i = blockIdx.x * blockDim.x + threadIdx.x;
    if (i < total4) {
        float4 v = ((const float4*)x)[i];
        ((float4*)h)[i] = v;
        ((float4*)agg)[i] = v;
    }
}

// ---------------- edge scatter (warp per edge) + fused stats zero ----------------
__global__ void scatter_k(const float* __restrict__ h, float* __restrict__ agg,
                          const int* __restrict__ ei, int E) {
    if (blockIdx.x == 0 && threadIdx.x < 256) g_stats[threadIdx.x] = 0.f;
    int warp = blockIdx.x * (blockDim.x >> 5) + (threadIdx.x >> 5);
    int lane = threadIdx.x & 31;
    if (warp >= E) return;
    int s = __ldg(ei + warp);
    int d = __ldg(ei + E + warp);
    float4 v = __ldg((const float4*)(h + (size_t)s * HD) + lane);
    float* dp = agg + (size_t)d * HD + lane * 4;
    asm volatile("red.global.add.v4.f32 [%0], {%1,%2,%3,%4};"
                 :: "l"(dp), "f"(v.x), "f"(v.y), "f"(v.z), "f"(v.w) : "memory");
}

// ---------------- mma.sync GEMM: out[M,128] = act(A[M,K] @ W + bias) ----------------
// 3-term bf16 hi/lo split. Block 128x128, 8 warps, warp = 16 rows x 128 cols.
// W hi/lo staged in smem with +8 bf16 row pad (ldmatrix bank-conflict free).
__global__ void __launch_bounds__(256, 1) gemm_mma(
    const float* __restrict__ A, const __nv_bfloat16* __restrict__ bth,
    const float* __restrict__ bias, float* __restrict__ out,
    int M, int K, int relu) {
    extern __shared__ __align__(16) __nv_bfloat16 ws[];
    const int tid = threadIdx.x;
    const int warp = tid >> 5;
    const int lane = tid & 31;
    const int fr = lane >> 2;          // 0..7
    const int fc = (lane & 3) * 2;     // 0,2,4,6
    const int rowBase = blockIdx.x * 128;
    const int warpRow = rowBase + warp * 16;
    const __nv_bfloat16* btl = bth + (size_t)128 * K;

    const int r0 = warpRow + fr;
    const int r1 = warpRow + 8 + fr;
    const bool v0 = r0 < M, v1 = r1 < M;

    // ldmatrix lane -> (row-within-pair, k-half) decode
    const int ll = lane & 7;
    const int selk = (lane >> 3) & 1;
    const int seln = (lane >> 4) & 1;

    float acc[16][4];
#pragma unroll
    for (int t = 0; t < 16; t++)
#pragma unroll
        for (int i = 0; i < 4; i++) acc[t][i] = 0.f;

    for (int k0 = 0; k0 < K; k0 += 128) {
        const int ck = min(128, K - k0);
        const int stride = ck + 8;
        const int kv8 = ck >> 3;    // uint4 per row
        // cooperative load of W hi & lo chunk into smem
        for (int i = tid; i < 128 * kv8; i += 256) {
            int n = i / kv8, kk = (i % kv8) * 8;
            *(uint4*)&ws[n * stride + kk] = *(const uint4*)&bth[(size_t)n * K + k0 + kk];
            *(uint4*)&ws[(128 + n) * stride + kk] = *(const uint4*)&btl[(size_t)n * K + k0 + kk];
        }
        __syncthreads();

        const uint32_t swb = smem_to_u32(ws);
        for (int ks = 0; ks < ck; ks += 16) {
            // ---- A fragments from gmem, converted to bf16 hi/lo ----
            const float* a0p = A + (size_t)r0 * K + k0 + ks + fc;
            const float* a1p = A + (size_t)r1 * K + k0 + ks + fc;
            float2 z = make_float2(0.f, 0.f);
            float2 x00 = v0 ? __ldg((const float2*)a0p)       : z;
            float2 x02 = v0 ? __ldg((const float2*)(a0p + 8)) : z;
            float2 x10 = v1 ? __ldg((const float2*)a1p)       : z;
            float2 x12 = v1 ? __ldg((const float2*)(a1p + 8)) : z;
            uint32_t ah[4], al[4];
            cvt_hilo(x00, ah[0], al[0]);
            cvt_hilo(x10, ah[1], al[1]);
            cvt_hilo(x02, ah[2], al[2]);
            cvt_hilo(x12, ah[3], al[3]);

            // ---- per n-tile pair: ldmatrix B hi/lo, 6 mma ----
#pragma unroll
            for (int ntp = 0; ntp < 8; ntp++) {
                int brow = ntp * 16 + seln * 8 + ll;
                int bcol = ks + selk * 8;
                uint32_t ahAddr = swb + (uint32_t)(brow * stride + bcol) * 2;
                uint32_t alAddr = ahAddr + (uint32_t)(128 * stride) * 2;
                uint32_t bh0, bh1, bh2, bh3, bl0, bl1, bl2, bl3;
                LDSM4(bh0, bh1, bh2, bh3, ahAddr);
                LDSM4(bl0, bl1, bl2, bl3, alAddr);
                MMA_BF16(acc[2 * ntp],     ah, bh0, bh1);
                MMA_BF16(acc[2 * ntp + 1], ah, bh2, bh3);
                MMA_BF16(acc[2 * ntp],     ah, bl0, bl1);
                MMA_BF16(acc[2 * ntp + 1], ah, bl2, bl3);
                MMA_BF16(acc[2 * ntp],     al, bh0, bh1);
                MMA_BF16(acc[2 * ntp + 1], al, bh2, bh3);
            }
        }
        __syncthreads();
    }

    // ---- epilogue: bias (+relu), store ----
    float* o0 = out + (size_t)r0 * 128;
    float* o1 = out + (size_t)r1 * 128;
#pragma unroll
    for (int nt = 0; nt < 16; nt++) {
        int c = nt * 8 + fc;
        float bx = __ldg(bias + c), by = __ldg(bias + c + 1);
        float2 w0 = make_float2(acc[nt][0] + bx, acc[nt][1] + by);
        float2 w1 = make_float2(acc[nt][2] + bx, acc[nt][3] + by);
        if (relu) {
            w0.x = fmaxf(w0.x, 0.f); w0.y = fmaxf(w0.y, 0.f);
            w1.x = fmaxf(w1.x, 0.f); w1.y = fmaxf(w1.y, 0.f);
        }
        if (v0) *(float2*)(o0 + c) = w0;
        if (v1) *(float2*)(o1 + c) = w1;
    }
}

// ---------------- BN stats: column sum / sumsq ----------------
__global__ void stats_k(const float* __restrict__ z, float* __restrict__ stats, int n) {
    __shared__ float ss[256], sq[256];
    int c = threadIdx.x & 127;
    int half = threadIdx.x >> 7;
    float s = 0.f, q = 0.f;
    for (int r = blockIdx.x * 2 + half; r < n; r += gridDim.x * 2) {
        float v = z[(size_t)r * 128 + c];
        s += v; q += v * v;
    }
    ss[threadIdx.x] = s; sq[threadIdx.x] = q;
    __syncthreads();
    if (threadIdx.x < 128) {
        atomicAdd(&stats[threadIdx.x], ss[threadIdx.x] + ss[threadIdx.x + 128]);
        atomicAdd(&stats[128 + threadIdx.x], sq[threadIdx.x] + sq[threadIdx.x + 128]);
    }
}

// ---------------- BN apply (+relu), writes h and (optionally) agg ----------------
__global__ void bn_apply_k(const float* __restrict__ z, const float* __restrict__ stats,
                           const float* __restrict__ gamma, const float* __restrict__ beta,
                           float* __restrict__ h, float* __restrict__ agg,
                           int n, int doRelu, int doAgg, float invN) {
    __shared__ float sc[128], sh[128];
    if (threadIdx.x < 128) {
        float mu = stats[threadIdx.x] * invN;
        float q = stats[128 + threadIdx.x] * invN;
        float var = q - mu * mu;
        float is = rsqrtf(var + 1e-5f);
        float s = is * gamma[threadIdx.x];
        sc[threadIdx.x] = s;
        sh[threadIdx.x] = beta[threadIdx.x] - mu * s;
    }
    __syncthreads();
    int total = n * 32;
    for (int i = blockIdx.x * blockDim.x + threadIdx.x; i < total;
         i += gridDim.x * blockDim.x) {
        int c = (i & 31) * 4;
        float4 v = ((const float4*)z)[i];
        float4 r;
        r.x = v.x * sc[c + 0] + sh[c + 0];
        r.y = v.y * sc[c + 1] + sh[c + 1];
        r.z = v.z * sc[c + 2] + sh[c + 2];
        r.w = v.w * sc[c + 3] + sh[c + 3];
        if (doRelu) {
            r.x = fmaxf(r.x, 0.f); r.y = fmaxf(r.y, 0.f);
            r.z = fmaxf(r.z, 0.f); r.w = fmaxf(r.w, 0.f);
        }
        ((float4*)h)[i] = r;
        if (doAgg) ((float4*)agg)[i] = r;
    }
}

// ---------------- pooling ----------------
__global__ void pool_init_k(int B) {
    int i = blockIdx.x * blockDim.x + threadIdx.x;
    if (i < B * HD) { g_ssum[i] = 0.f; g_smax[i] = 0x007FFFFFu; }
    if (i < B) g_cnt[i] = 0;
}

__global__ void pool_k(const float* __restrict__ h, const int* __restrict__ batch, int n) {
    const int t = threadIdx.x;
    int start = blockIdx.x * 256;
    int end = min(start + 256, n);
    if (start >= end) return;
    int cur = __ldg(batch + start);
    float s = 0.f, m = NEG_INF;
    int c = 0;
    for (int v0 = start; v0 < end; v0 += 8) {
        float vals[8]; int bs[8];
        int mm = min(8, end - v0);
#pragma unroll
        for (int k = 0; k < 8; k++) {
            if (k < mm) {
                vals[k] = __ldg(h + (size_t)(v0 + k) * HD + t);
                bs[k] = __ldg(batch + v0 + k);
            }
        }
        for (int k = 0; k < mm; k++) {
            if (bs[k] != cur) {
                atomicAdd(&g_ssum[cur * HD + t], s);
                atomicMax(&g_smax[cur * HD + t], fenc(m));
                if (t == 0) atomicAdd(&g_cnt[cur], c);
                cur = bs[k]; s = 0.f; m = NEG_INF; c = 0;
            }
            s += vals[k]; m = fmaxf(m, vals[k]); c++;
        }
    }
    atomicAdd(&g_ssum[cur * HD + t], s);
    atomicMax(&g_smax[cur * HD + t], fenc(m));
    if (t == 0) atomicAdd(&g_cnt[cur], c);
}

__global__ void graph_k(int B) {
    int i = blockIdx.x * blockDim.x + threadIdx.x;
    if (i >= B * 384) return;
    int b = i / 384, c = i % 384;
    float o;
    if (c < 128) {
        o = g_ssum[b * HD + c] / (float)max(g_cnt[b], 1);
    } else if (c < 256) {
        o = (g_cnt[b] == 0) ? 0.f : fdec(g_smax[b * HD + c - 128]);
    } else {
        o = g_ssum[b * HD + (c - 256)];
    }
    g_graph[i] = o;
}

__global__ void comb_k(int rows) {
    int i = blockIdx.x * blockDim.x + threadIdx.x;
    int total = rows * 128;
    if (i >= total) return;
    int r = i >> 7, c4 = i & 127;
    float4 v;
    if (c4 < 96) v = *(const float4*)&g_graph[(r >> 5) * 384 + c4 * 4];
    else         v = *(const float4*)&g_oe[(size_t)r * HD + (c4 - 96) * 4];
    ((float4*)g_comb)[i] = v;
}

// ---------------- SIMT GEMM for NT=64 head layer ----------------
template <int NT, bool RELU>
__global__ __launch_bounds__(2 * NT, 2)
void gemm_k(const float* __restrict__ A, const float* __restrict__ W,
            const float* __restrict__ bias, float* __restrict__ out, int M, int K) {
    constexpr int THREADS = 2 * NT;
    constexpr int TX = NT / 8;
    __shared__ float As[32][128];
    __shared__ float Bs[32][NT];
    const int tid = threadIdx.x;
    const int tx = tid % TX;
    const int ty = tid / TX;
    const int rowBase = blockIdx.x * 128;
    float acc[8][8];
#pragma unroll
    for (int j = 0; j < 8; j++)
#pragma unroll
        for (int i = 0; i < 8; i++) acc[j][i] = 0.f;
    for (int kt = 0; kt < K; kt += 32) {
#pragma unroll
        for (int q0 = 0; q0 < 1024 / THREADS; q0++) {
            int q = q0 * THREADS + tid;
            int r = q >> 3;
            int kq = (q & 7) * 4;
            float4 v = make_float4(0.f, 0.f, 0.f, 0.f);
            int gr = rowBase + r;
            if (gr < M) v = *(const float4*)(A + (size_t)gr * K + kt + kq);
            As[kq + 0][r] = v.x; As[kq + 1][r] = v.y;
            As[kq + 2][r] = v.z; As[kq + 3][r] = v.w;
        }
#pragma unroll
        for (int q0 = 0; q0 < (32 * NT / 4) / THREADS; q0++) {
            int q = q0 * THREADS + tid;
            int kl = q / (NT / 4);
            int c4 = (q % (NT / 4)) * 4;
            *(float4*)&Bs[kl][c4] = *(const float4*)(W + (size_t)(kt + kl) * NT + c4);
        }
        __syncthreads();
#pragma unroll
        for (int kl = 0; kl < 32; kl++) {
            float a[8], b[8];
            *(float4*)&a[0] = *(const float4*)&As[kl][ty * 8];
            *(float4*)&a[4] = *(const float4*)&As[kl][ty * 8 + 4];
            *(float4*)&b[0] = *(const float4*)&Bs[kl][tx * 8];
            *(float4*)&b[4] = *(const float4*)&Bs[kl][tx * 8 + 4];
#pragma unroll
            for (int j = 0; j < 8; j++)
#pragma unroll
                for (int i = 0; i < 8; i++)
                    acc[j][i] = fmaf(a[j], b[i], acc[j][i]);
        }
        __syncthreads();
    }
    float br[8];
#pragma unroll
    for (int i = 0; i < 8; i++) br[i] = __ldg(bias + tx * 8 + i);
#pragma unroll
    for (int j = 0; j < 8; j++) {
        int gr = rowBase + ty * 8 + j;
        if (gr >= M) continue;
        float v[8];
#pragma unroll
        for (int i = 0; i < 8; i++) {
            v[i] = acc[j][i] + br[i];
            if (RELU) v[i] = fmaxf(v[i], 0.f);
        }
        float* op = out + (size_t)gr * NT + tx * 8;
        *(float4*)op       = make_float4(v[0], v[1], v[2], v[3]);
        *(float4*)(op + 4) = make_float4(v[4], v[5], v[6], v[7]);
    }
}

// ---------------- final dot ----------------
__global__ void s3_k(const float* __restrict__ s2, const float* __restrict__ W,
                     const float* __restrict__ b, float* __restrict__ out, int rows) {
    int warp = (blockIdx.x * blockDim.x + threadIdx.x) >> 5;
    int lane = threadIdx.x & 31;
    if (warp >= rows) return;
    const float* row = s2 + (size_t)warp * 64;
    float s = row[lane] * W[lane] + row[lane + 32] * W[lane + 32];
#pragma unroll
    for (int o = 16; o > 0; o >>= 1) s += __shfl_down_sync(0xffffffffu, s, o);
    if (lane == 0) out[warp] = s + b[0];
}

// ---------------- launch ----------------
extern "C" void kernel_launch(void* const* d_in, const int* in_sizes, int n_in,
                              void* d_out, int out_size) {
    const float* x      = (const float*)d_in[0];
    const int*   ei     = (const int*)d_in[1];
    const float* orders = (const float*)d_in[2];
    const int*   batch  = (const int*)d_in[3];
    const float* gW1    = (const float*)d_in[4];
    const float* gb1    = (const float*)d_in[5];
    const float* gW2    = (const float*)d_in[6];
    const float* gb2    = (const float*)d_in[7];
    const float* gamma  = (const float*)d_in[8];
    const float* beta   = (const float*)d_in[9];
    const float* oW1    = (const float*)d_in[10];
    const float* ob1    = (const float*)d_in[11];
    const float* oW2    = (const float*)d_in[12];
    const float* ob2    = (const float*)d_in[13];
    const float* sW1    = (const float*)d_in[14];
    const float* sb1    = (const float*)d_in[15];
    const float* sW2    = (const float*)d_in[16];
    const float* sb2    = (const float*)d_in[17];
    const float* sW3    = (const float*)d_in[18];
    const float* sb3    = (const float*)d_in[19];
    float* out = (float*)d_out;

    const int n = in_sizes[0] / HD;
    const int E = in_sizes[1] / 2;
    const int B = in_sizes[2] / (OMAX * 32);
    const int L = in_sizes[4] / (HD * HD);
    const int rows = B * OMAX;

    float *hB, *aggB, *z1B, *statsB, *oeB, *combB, *s1B, *s2B;
    __nv_bfloat16* wbfB;
    cudaGetSymbolAddress((void**)&hB, g_h);
    cudaGetSymbolAddress((void**)&aggB, g_agg);
    cudaGetSymbolAddress((void**)&z1B, g_z1);
    cudaGetSymbolAddress((void**)&statsB, g_stats);
    cudaGetSymbolAddress((void**)&oeB, g_oe);
    cudaGetSymbolAddress((void**)&combB, g_comb);
    cudaGetSymbolAddress((void**)&s1B, g_s1);
    cudaGetSymbolAddress((void**)&s2B, g_s2);
    cudaGetSymbolAddress((void**)&wbfB, g_wbf);

    static int smemSet = 0;
    if (!smemSet) {
        cudaFuncSetAttribute(gemm_mma, cudaFuncAttributeMaxDynamicSharedMemorySize, 73728);
        smemSet = 1;
    }

    // smem bytes for gemm_mma: 2 tiles * 128 rows * (ck+8) bf16
    auto smemFor = [](int K) { int ck = K < 128 ? K : 128; return (size_t)2 * 128 * (ck + 8) * 2; };

    prep_k<<<720, 256>>>(gW1, gW2, oW1, oW2, sW1);

    const int f4n = n * 32;
    init_copy_k<<<(f4n + 255) / 256, 256>>>(x, hB, aggB, f4n);

    const int gGrid = (n + 127) / 128;
    const size_t sm128 = smemFor(128);
    for (int l = 0; l < L; l++) {
        scatter_k<<<(E + 7) / 8, 256>>>(hB, aggB, ei, E);
        gemm_mma<<<gGrid, 256, sm128>>>(aggB, wbfB + (size_t)l * 32768,
                                        gb1 + l * HD, z1B, n, HD, 1);
        gemm_mma<<<gGrid, 256, sm128>>>(z1B, wbfB + 98304 + (size_t)l * 32768,
                                        gb2 + l * HD, aggB, n, HD, 0);
        stats_k<<<1024, 256>>>(aggB, statsB, n);
        int last = (l == L - 1);
        bn_apply_k<<<4096, 256>>>(aggB, statsB, gamma + l * HD, beta + l * HD,
                                  hB, aggB, n, !last, !last, 1.0f / (float)n);
    }

    pool_init_k<<<(B * HD + 255) / 256, 256>>>(B);
    pool_k<<<(n + 255) / 256, 128>>>(hB, batch, n);
    graph_k<<<(B * 384 + 255) / 256, 256>>>(B);

    const int hGrid = (rows + 127) / 128;
    gemm_mma<<<hGrid, 256, smemFor(32)>>>(orders, wbfB + 196608, ob1, z1B, rows, 32, 1);
    gemm_mma<<<hGrid, 256, sm128>>>(z1B, wbfB + 204800, ob2, oeB, rows, HD, 0);
    comb_k<<<(rows * 128 + 255) / 256, 256>>>(rows);
    gemm_mma<<<hGrid, 256, sm128>>>(combB, wbfB + 237568, sb1, s1B, rows, 512, 1);
    gemm_k<64, true><<<hGrid, 128>>>(s1B, sW2, sb2, s2B, rows, HD);
    s3_k<<<(rows + 7) / 8, 256>>>(s2B, sW3, sb3, out, rows);
}

// round 4
// speedup vs baseline: 1.9745x; 1.7427x over previous
#include <cuda_runtime.h>
#include <cuda_bf16.h>
#include <cstdint>

#define NMAX 100000
#define EMAX 1600000
#define HD   128
#define BMAX 256
#define OMAX 32

// ---------------- static scratch ----------------
__device__ float    g_h   [NMAX * HD];
__device__ float    g_agg [NMAX * HD];
__device__ float    g_z1  [NMAX * HD];
__device__ float    g_stats[2 * HD];
__device__ float    g_ssum[BMAX * HD];
__device__ unsigned g_smax[BMAX * HD];
__device__ int      g_cnt [BMAX];
__device__ float    g_graph[BMAX * 384];
__device__ float    g_oe  [BMAX * OMAX * HD];
__device__ float    g_comb[BMAX * OMAX * 512];
__device__ float    g_s1  [BMAX * OMAX * HD];
__device__ float    g_s2  [BMAX * OMAX * 64];
__device__ uint4    g_wfrag[46080];          // fragment-ordered hi/lo bf16 weights
// CSR
__device__ int      g_deg   [NMAX];
__device__ int      g_rowptr[NMAX + 1];
__device__ int      g_cursor[NMAX];
__device__ int      g_ssrc  [EMAX];
__device__ int      g_bsum  [256];
__device__ int      g_boff  [256];

// mma.sync bf16 m16n8k16
#define MMA_BF16(c, a, b0, b1) \
    asm volatile("mma.sync.aligned.m16n8k16.row.col.f32.bf16.bf16.f32 " \
        "{%0,%1,%2,%3}, {%4,%5,%6,%7}, {%8,%9}, {%0,%1,%2,%3};" \
        : "+f"((c)[0]), "+f"((c)[1]), "+f"((c)[2]), "+f"((c)[3]) \
        : "r"((a)[0]), "r"((a)[1]), "r"((a)[2]), "r"((a)[3]), "r"(b0), "r"(b1))

__device__ __forceinline__ void cvt_hilo(float2 v, uint32_t& hi, uint32_t& lo) {
    __nv_bfloat162 h = __float22bfloat162_rn(v);
    float hx = __bfloat162float(h.x), hy = __bfloat162float(h.y);
    __nv_bfloat162 l = __float22bfloat162_rn(make_float2(v.x - hx, v.y - hy));
    hi = *(uint32_t*)&h;
    lo = *(uint32_t*)&l;
}

__device__ __forceinline__ unsigned fenc(float f) {
    unsigned u = __float_as_uint(f);
    return (u & 0x80000000u) ? ~u : (u | 0x80000000u);
}
__device__ __forceinline__ float fdec(unsigned u) {
    unsigned b = (u & 0x80000000u) ? (u & 0x7FFFFFFFu) : ~u;
    return __uint_as_float(b);
}
#define NEG_INF __uint_as_float(0xff800000u)

// ---------------- weight prep: fragment-ordered hi/lo bf16 ----------------
// per gemm (N=128): u32 idx el: ks = el/2048; ntile = (el%2048)/128; lane = (el%128)/4; q = el%4
// n = ntile*8 + lane/4; k = ks*16 + (lane%4)*2 + (q&1)*8; q<2 -> hi, else lo
__global__ void prep_k(const float* __restrict__ gW1, const float* __restrict__ gW2,
                       const float* __restrict__ oW1f, const float* __restrict__ oW2f,
                       const float* __restrict__ sW1f) {
    int idx = blockIdx.x * blockDim.x + threadIdx.x;
    if (idx >= 184320) return;
    const float* W; int el;
    if (idx < 98304) {
        int m = idx / 16384; el = idx % 16384;
        W = (m < 3) ? gW1 + (size_t)m * 16384 : gW2 + (size_t)(m - 3) * 16384;
    } else if (idx < 102400) { el = idx - 98304;  W = oW1f; }
    else if   (idx < 118784) { el = idx - 102400; W = oW2f; }
    else                     { el = idx - 118784; W = sW1f; }
    int ks = el >> 11;
    int rem = el & 2047;
    int ntile = rem >> 7;
    int lane = (rem & 127) >> 2;
    int q = rem & 3;
    int n = ntile * 8 + (lane >> 2);
    int k = ks * 16 + (lane & 3) * 2 + ((q & 1) ? 8 : 0);
    float v0 = W[(size_t)k * 128 + n];
    float v1 = W[(size_t)(k + 1) * 128 + n];
    uint32_t r;
    if (q < 2) {
        __nv_bfloat16 h0 = __float2bfloat16(v0), h1 = __float2bfloat16(v1);
        r = ((uint32_t)__bfloat16_as_ushort(h1) << 16) | __bfloat16_as_ushort(h0);
    } else {
        __nv_bfloat16 h0 = __float2bfloat16(v0), h1 = __float2bfloat16(v1);
        __nv_bfloat16 l0 = __float2bfloat16(v0 - __bfloat162float(h0));
        __nv_bfloat16 l1 = __float2bfloat16(v1 - __bfloat162float(h1));
        r = ((uint32_t)__bfloat16_as_ushort(l1) << 16) | __bfloat16_as_ushort(l0);
    }
    ((uint32_t*)g_wfrag)[idx] = r;
}

// ---------------- init: h = x ----------------
__global__ void init_copy_k(const float* __restrict__ x, float* __restrict__ h, int total4) {
    int i = blockIdx.x * blockDim.x + threadIdx.x;
    if (i < total4) ((float4*)h)[i] = ((const float4*)x)[i];
}

// ---------------- CSR build ----------------
__global__ void zero_deg_k(int n) {
    int i = blockIdx.x * blockDim.x + threadIdx.x;
    if (i < n) g_deg[i] = 0;
}
__global__ void hist_k(const int* __restrict__ ei, int E) {
    int i = blockIdx.x * blockDim.x + threadIdx.x;
    if (i < E) atomicAdd(&g_deg[__ldg(ei + E + i)], 1);
}
__global__ void partial_k(int n) {
    __shared__ int sd[256];
    int C = (n + 255) / 256;
    int start = blockIdx.x * C, end = min(start + C, n);
    int s = 0;
    for (int i = start + threadIdx.x; i < end; i += 256) s += g_deg[i];
    sd[threadIdx.x] = s;
    __syncthreads();
    for (int o = 128; o > 0; o >>= 1) {
        if (threadIdx.x < o) sd[threadIdx.x] += sd[threadIdx.x + o];
        __syncthreads();
    }
    if (threadIdx.x == 0) g_bsum[blockIdx.x] = sd[0];
}
__global__ void scanb_k() {
    __shared__ int sd[256];
    int t = threadIdx.x;
    sd[t] = g_bsum[t];
    __syncthreads();
    for (int o = 1; o < 256; o <<= 1) {
        int v = (t >= o) ? sd[t - o] : 0;
        __syncthreads();
        sd[t] += v;
        __syncthreads();
    }
    g_boff[t] = sd[t] - g_bsum[t];
}
__global__ void rowptr_k(int n, int E) {
    __shared__ int sd[256];
    int C = (n + 255) / 256;
    int start = blockIdx.x * C, end = min(start + C, n);
    int off = g_boff[blockIdx.x];
    for (int base = start; base < end; base += 256) {
        int i = base + threadIdx.x;
        int d = (i < end) ? g_deg[i] : 0;
        sd[threadIdx.x] = d;
        __syncthreads();
        for (int o = 1; o < 256; o <<= 1) {
            int v = (threadIdx.x >= o) ? sd[threadIdx.x - o] : 0;
            __syncthreads();
            sd[threadIdx.x] += v;
            __syncthreads();
        }
        if (i < end) {
            int ex = off + sd[threadIdx.x] - d;
            g_rowptr[i] = ex;
            g_cursor[i] = ex;
        }
        int tot = sd[255];
        __syncthreads();
        off += tot;
    }
    if (blockIdx.x == 255 && threadIdx.x == 0) g_rowptr[n] = E;
}
__global__ void fill_k(const int* __restrict__ ei, int E) {
    int i = blockIdx.x * blockDim.x + threadIdx.x;
    if (i >= E) return;
    int s = __ldg(ei + i);
    int d = __ldg(ei + E + i);
    int pos = atomicAdd(&g_cursor[d], 1);
    g_ssrc[pos] = s;
}

// ---------------- gather: agg[d] = h[d] + sum_{src in N(d)} h[src] ----------------
__global__ void gather_k(const float* __restrict__ h, float* __restrict__ agg, int n) {
    if (blockIdx.x == 0 && threadIdx.x < 256) g_stats[threadIdx.x] = 0.f;
    int wid = blockIdx.x * (blockDim.x >> 5) + (threadIdx.x >> 5);
    int lane = threadIdx.x & 31;
    if (wid >= n) return;
    int beg = __ldg(&g_rowptr[wid]);
    int end = __ldg(&g_rowptr[wid + 1]);
    const float4* h4 = (const float4*)h;
    float4 acc = __ldg(h4 + (size_t)wid * 32 + lane);
    int j = beg;
    for (; j + 4 <= end; j += 4) {
        int s0 = __ldg(&g_ssrc[j]);
        int s1 = __ldg(&g_ssrc[j + 1]);
        int s2 = __ldg(&g_ssrc[j + 2]);
        int s3 = __ldg(&g_ssrc[j + 3]);
        float4 v0 = __ldg(h4 + (size_t)s0 * 32 + lane);
        float4 v1 = __ldg(h4 + (size_t)s1 * 32 + lane);
        float4 v2 = __ldg(h4 + (size_t)s2 * 32 + lane);
        float4 v3 = __ldg(h4 + (size_t)s3 * 32 + lane);
        acc.x += v0.x + v1.x + v2.x + v3.x;
        acc.y += v0.y + v1.y + v2.y + v3.y;
        acc.z += v0.z + v1.z + v2.z + v3.z;
        acc.w += v0.w + v1.w + v2.w + v3.w;
    }
    for (; j < end; j++) {
        int s = __ldg(&g_ssrc[j]);
        float4 v = __ldg(h4 + (size_t)s * 32 + lane);
        acc.x += v.x; acc.y += v.y; acc.z += v.z; acc.w += v.w;
    }
    ((float4*)agg)[(size_t)wid * 32 + lane] = acc;
}

// ---------------- fragment-ordered mma GEMM: out[M,128] = act(A[M,K]@W + b) ----------------
// 128 threads (4 warps), block = 64 rows. No smem, no barriers.
__global__ void __launch_bounds__(128) gemm_f(
    const float* __restrict__ A, const uint4* __restrict__ wf,
    const float* __restrict__ bias, float* __restrict__ out,
    int M, int K, int relu) {
    const int lane = threadIdx.x & 31;
    const int warp = threadIdx.x >> 5;
    const int fr = lane >> 2;
    const int c2 = (lane & 3) * 2;
    const int rowBase = blockIdx.x * 64 + warp * 16;
    const int r0 = rowBase + fr;
    const int r1 = r0 + 8;
    const bool v0 = r0 < M, v1 = r1 < M;
    const uint4* wp = wf + lane;

    float acc[16][4];
#pragma unroll
    for (int t = 0; t < 16; t++)
#pragma unroll
        for (int i = 0; i < 4; i++) acc[t][i] = 0.f;

    const int nks = K >> 4;
    const float2 z = make_float2(0.f, 0.f);
    for (int ks = 0; ks < nks; ks++) {
        const float* a0p = A + (size_t)r0 * K + ks * 16 + c2;
        const float* a1p = A + (size_t)r1 * K + ks * 16 + c2;
        float2 x00 = v0 ? __ldg((const float2*)a0p)       : z;
        float2 x10 = v1 ? __ldg((const float2*)a1p)       : z;
        float2 x02 = v0 ? __ldg((const float2*)(a0p + 8)) : z;
        float2 x12 = v1 ? __ldg((const float2*)(a1p + 8)) : z;
        uint32_t ah[4], al[4];
        cvt_hilo(x00, ah[0], al[0]);
        cvt_hilo(x10, ah[1], al[1]);
        cvt_hilo(x02, ah[2], al[2]);
        cvt_hilo(x12, ah[3], al[3]);
        const uint4* wk = wp + ks * 512;
#pragma unroll
        for (int nt = 0; nt < 16; nt++) {
            uint4 w = __ldg(wk + nt * 32);
            MMA_BF16(acc[nt], ah, w.x, w.y);   // ahi * bhi
            MMA_BF16(acc[nt], ah, w.z, w.w);   // ahi * blo
            MMA_BF16(acc[nt], al, w.x, w.y);   // alo * bhi
        }
    }

    float* o0 = out + (size_t)r0 * 128;
    float* o1 = out + (size_t)r1 * 128;
#pragma unroll
    for (int nt = 0; nt < 16; nt++) {
        int c = nt * 8 + c2;
        float bx = __ldg(bias + c), by = __ldg(bias + c + 1);
        float2 w0 = make_float2(acc[nt][0] + bx, acc[nt][1] + by);
        float2 w1 = make_float2(acc[nt][2] + bx, acc[nt][3] + by);
        if (relu) {
            w0.x = fmaxf(w0.x, 0.f); w0.y = fmaxf(w0.y, 0.f);
            w1.x = fmaxf(w1.x, 0.f); w1.y = fmaxf(w1.y, 0.f);
        }
        if (v0) *(float2*)(o0 + c) = w0;
        if (v1) *(float2*)(o1 + c) = w1;
    }
}

// ---------------- BN stats ----------------
__global__ void stats_k(const float* __restrict__ z, float* __restrict__ stats, int n) {
    __shared__ float ss[256], sq[256];
    int c = threadIdx.x & 127;
    int half = threadIdx.x >> 7;
    float s = 0.f, q = 0.f;
    for (int r = blockIdx.x * 2 + half; r < n; r += gridDim.x * 2) {
        float v = z[(size_t)r * 128 + c];
        s += v; q += v * v;
    }
    ss[threadIdx.x] = s; sq[threadIdx.x] = q;
    __syncthreads();
    if (threadIdx.x < 128) {
        atomicAdd(&stats[threadIdx.x], ss[threadIdx.x] + ss[threadIdx.x + 128]);
        atomicAdd(&stats[128 + threadIdx.x], sq[threadIdx.x] + sq[threadIdx.x + 128]);
    }
}

// ---------------- BN apply (+relu) -> h ----------------
__global__ void bn_apply_k(const float* __restrict__ z, const float* __restrict__ stats,
                           const float* __restrict__ gamma, const float* __restrict__ beta,
                           float* __restrict__ h, int n, int doRelu, float invN) {
    __shared__ float sc[128], sh[128];
    if (threadIdx.x < 128) {
        float mu = stats[threadIdx.x] * invN;
        float q = stats[128 + threadIdx.x] * invN;
        float var = q - mu * mu;
        float is = rsqrtf(var + 1e-5f);
        float s = is * gamma[threadIdx.x];
        sc[threadIdx.x] = s;
        sh[threadIdx.x] = beta[threadIdx.x] - mu * s;
    }
    __syncthreads();
    int total = n * 32;
    for (int i = blockIdx.x * blockDim.x + threadIdx.x; i < total;
         i += gridDim.x * blockDim.x) {
        int c = (i & 31) * 4;
        float4 v = ((const float4*)z)[i];
        float4 r;
        r.x = v.x * sc[c + 0] + sh[c + 0];
        r.y = v.y * sc[c + 1] + sh[c + 1];
        r.z = v.z * sc[c + 2] + sh[c + 2];
        r.w = v.w * sc[c + 3] + sh[c + 3];
        if (doRelu) {
            r.x = fmaxf(r.x, 0.f); r.y = fmaxf(r.y, 0.f);
            r.z = fmaxf(r.z, 0.f); r.w = fmaxf(r.w, 0.f);
        }
        ((float4*)h)[i] = r;
    }
}

// ---------------- pooling ----------------
__global__ void pool_init_k(int B) {
    int i = blockIdx.x * blockDim.x + threadIdx.x;
    if (i < B * HD) { g_ssum[i] = 0.f; g_smax[i] = 0x007FFFFFu; }
    if (i < B) g_cnt[i] = 0;
}
__global__ void pool_k(const float* __restrict__ h, const int* __restrict__ batch, int n) {
    const int t = threadIdx.x;
    int start = blockIdx.x * 256;
    int end = min(start + 256, n);
    if (start >= end) return;
    int cur = __ldg(batch + start);
    float s = 0.f, m = NEG_INF;
    int c = 0;
    for (int v0 = start; v0 < end; v0 += 8) {
        float vals[8]; int bs[8];
        int mm = min(8, end - v0);
#pragma unroll
        for (int k = 0; k < 8; k++) {
            if (k < mm) {
                vals[k] = __ldg(h + (size_t)(v0 + k) * HD + t);
                bs[k] = __ldg(batch + v0 + k);
            }
        }
        for (int k = 0; k < mm; k++) {
            if (bs[k] != cur) {
                atomicAdd(&g_ssum[cur * HD + t], s);
                atomicMax(&g_smax[cur * HD + t], fenc(m));
                if (t == 0) atomicAdd(&g_cnt[cur], c);
                cur = bs[k]; s = 0.f; m = NEG_INF; c = 0;
            }
            s += vals[k]; m = fmaxf(m, vals[k]); c++;
        }
    }
    atomicAdd(&g_ssum[cur * HD + t], s);
    atomicMax(&g_smax[cur * HD + t], fenc(m));
    if (t == 0) atomicAdd(&g_cnt[cur], c);
}
__global__ void graph_k(int B) {
    int i = blockIdx.x * blockDim.x + threadIdx.x;
    if (i >= B * 384) return;
    int b = i / 384, c = i % 384;
    float o;
    if (c < 128)      o = g_ssum[b * HD + c] / (float)max(g_cnt[b], 1);
    else if (c < 256) o = (g_cnt[b] == 0) ? 0.f : fdec(g_smax[b * HD + c - 128]);
    else              o = g_ssum[b * HD + (c - 256)];
    g_graph[i] = o;
}
__global__ void comb_k(int rows) {
    int i = blockIdx.x * blockDim.x + threadIdx.x;
    int total = rows * 128;
    if (i >= total) return;
    int r = i >> 7, c4 = i & 127;
    float4 v;
    if (c4 < 96) v = *(const float4*)&g_graph[(r >> 5) * 384 + c4 * 4];
    else         v = *(const float4*)&g_oe[(size_t)r * HD + (c4 - 96) * 4];
    ((float4*)g_comb)[i] = v;
}

// ---------------- SIMT GEMM NT=64 ----------------
template <int NT, bool RELU>
__global__ __launch_bounds__(2 * NT, 2)
void gemm_k(const float* __restrict__ A, const float* __restrict__ W,
            const float* __restrict__ bias, float* __restrict__ out, int M, int K) {
    constexpr int THREADS = 2 * NT;
    constexpr int TX = NT / 8;
    __shared__ float As[32][128];
    __shared__ float Bs[32][NT];
    const int tid = threadIdx.x;
    const int tx = tid % TX;
    const int ty = tid / TX;
    const int rowBase = blockIdx.x * 128;
    float acc[8][8];
#pragma unroll
    for (int j = 0; j < 8; j++)
#pragma unroll
        for (int i = 0; i < 8; i++) acc[j][i] = 0.f;
    for (int kt = 0; kt < K; kt += 32) {
#pragma unroll
        for (int q0 = 0; q0 < 1024 / THREADS; q0++) {
            int q = q0 * THREADS + tid;
            int r = q >> 3;
            int kq = (q & 7) * 4;
            float4 v = make_float4(0.f, 0.f, 0.f, 0.f);
            int gr = rowBase + r;
            if (gr < M) v = *(const float4*)(A + (size_t)gr * K + kt + kq);
            As[kq + 0][r] = v.x; As[kq + 1][r] = v.y;
            As[kq + 2][r] = v.z; As[kq + 3][r] = v.w;
        }
#pragma unroll
        for (int q0 = 0; q0 < (32 * NT / 4) / THREADS; q0++) {
            int q = q0 * THREADS + tid;
            int kl = q / (NT / 4);
            int c4 = (q % (NT / 4)) * 4;
            *(float4*)&Bs[kl][c4] = *(const float4*)(W + (size_t)(kt + kl) * NT + c4);
        }
        __syncthreads();
#pragma unroll
        for (int kl = 0; kl < 32; kl++) {
            float a[8], b[8];
            *(float4*)&a[0] = *(const float4*)&As[kl][ty * 8];
            *(float4*)&a[4] = *(const float4*)&As[kl][ty * 8 + 4];
            *(float4*)&b[0] = *(const float4*)&Bs[kl][tx * 8];
            *(float4*)&b[4] = *(const float4*)&Bs[kl][tx * 8 + 4];
#pragma unroll
            for (int j = 0; j < 8; j++)
#pragma unroll
                for (int i = 0; i < 8; i++)
                    acc[j][i] = fmaf(a[j], b[i], acc[j][i]);
        }
        __syncthreads();
    }
    float br[8];
#pragma unroll
    for (int i = 0; i < 8; i++) br[i] = __ldg(bias + tx * 8 + i);
#pragma unroll
    for (int j = 0; j < 8; j++) {
        int gr = rowBase + ty * 8 + j;
        if (gr >= M) continue;
        float v[8];
#pragma unroll
        for (int i = 0; i < 8; i++) {
            v[i] = acc[j][i] + br[i];
            if (RELU) v[i] = fmaxf(v[i], 0.f);
        }
        float* op = out + (size_t)gr * NT + tx * 8;
        *(float4*)op       = make_float4(v[0], v[1], v[2], v[3]);
        *(float4*)(op + 4) = make_float4(v[4], v[5], v[6], v[7]);
    }
}

// ---------------- final dot ----------------
__global__ void s3_k(const float* __restrict__ s2, const float* __restrict__ W,
                     const float* __restrict__ b, float* __restrict__ out, int rows) {
    int warp = (blockIdx.x * blockDim.x + threadIdx.x) >> 5;
    int lane = threadIdx.x & 31;
    if (warp >= rows) return;
    const float* row = s2 + (size_t)warp * 64;
    float s = row[lane] * W[lane] + row[lane + 32] * W[lane + 32];
#pragma unroll
    for (int o = 16; o > 0; o >>= 1) s += __shfl_down_sync(0xffffffffu, s, o);
    if (lane == 0) out[warp] = s + b[0];
}

// ---------------- launch ----------------
extern "C" void kernel_launch(void* const* d_in, const int* in_sizes, int n_in,
                              void* d_out, int out_size) {
    const float* x      = (const float*)d_in[0];
    const int*   ei     = (const int*)d_in[1];
    const float* orders = (const float*)d_in[2];
    const int*   batch  = (const int*)d_in[3];
    const float* gW1    = (const float*)d_in[4];
    const float* gb1    = (const float*)d_in[5];
    const float* gW2    = (const float*)d_in[6];
    const float* gb2    = (const float*)d_in[7];
    const float* gamma  = (const float*)d_in[8];
    const float* beta   = (const float*)d_in[9];
    const float* oW1    = (const float*)d_in[10];
    const float* ob1    = (const float*)d_in[11];
    const float* oW2    = (const float*)d_in[12];
    const float* ob2    = (const float*)d_in[13];
    const float* sW1    = (const float*)d_in[14];
    const float* sb1    = (const float*)d_in[15];
    const float* sW2    = (const float*)d_in[16];
    const float* sb2    = (const float*)d_in[17];
    const float* sW3    = (const float*)d_in[18];
    const float* sb3    = (const float*)d_in[19];
    float* out = (float*)d_out;

    const int n = in_sizes[0] / HD;
    const int E = in_sizes[1] / 2;
    const int B = in_sizes[2] / (OMAX * 32);
    const int L = in_sizes[4] / (HD * HD);
    const int rows = B * OMAX;

    float *hB, *aggB, *z1B, *statsB, *oeB, *combB, *s1B, *s2B;
    uint4* wfB;
    cudaGetSymbolAddress((void**)&hB, g_h);
    cudaGetSymbolAddress((void**)&aggB, g_agg);
    cudaGetSymbolAddress((void**)&z1B, g_z1);
    cudaGetSymbolAddress((void**)&statsB, g_stats);
    cudaGetSymbolAddress((void**)&oeB, g_oe);
    cudaGetSymbolAddress((void**)&combB, g_comb);
    cudaGetSymbolAddress((void**)&s1B, g_s1);
    cudaGetSymbolAddress((void**)&s2B, g_s2);
    cudaGetSymbolAddress((void**)&wfB, g_wfrag);

    prep_k<<<720, 256>>>(gW1, gW2, oW1, oW2, sW1);

    const int f4n = n * 32;
    init_copy_k<<<(f4n + 255) / 256, 256>>>(x, hB, f4n);

    // CSR build (dst-sorted adjacency)
    zero_deg_k<<<(n + 255) / 256, 256>>>(n);
    hist_k<<<(E + 255) / 256, 256>>>(ei, E);
    partial_k<<<256, 256>>>(n);
    scanb_k<<<1, 256>>>();
    rowptr_k<<<256, 256>>>(n, E);
    fill_k<<<(E + 255) / 256, 256>>>(ei, E);

    const int gGrid = (n + 63) / 64;
    for (int l = 0; l < L; l++) {
        gather_k<<<(n + 7) / 8, 256>>>(hB, aggB, n);
        gemm_f<<<gGrid, 128>>>(aggB, wfB + (size_t)l * 4096, gb1 + l * HD, z1B, n, HD, 1);
        gemm_f<<<gGrid, 128>>>(z1B, wfB + (size_t)(3 + l) * 4096, gb2 + l * HD, aggB, n, HD, 0);
        stats_k<<<1024, 256>>>(aggB, statsB, n);
        int last = (l == L - 1);
        bn_apply_k<<<2048, 256>>>(aggB, statsB, gamma + l * HD, beta + l * HD,
                                  hB, n, !last, 1.0f / (float)n);
    }

    pool_init_k<<<(B * HD + 255) / 256, 256>>>(B);
    pool_k<<<(n + 255) / 256, 128>>>(hB, batch, n);
    graph_k<<<(B * 384 + 255) / 256, 256>>>(B);

    const int hGrid = (rows + 63) / 64;
    gemm_f<<<hGrid, 128>>>(orders, wfB + 24576, ob1, z1B, rows, 32, 1);
    gemm_f<<<hGrid, 128>>>(z1B, wfB + 25600, ob2, oeB, rows, HD, 0);
    comb_k<<<(rows * 128 + 255) / 256, 256>>>(rows);
    gemm_f<<<hGrid, 128>>>(combB, wfB + 29696, sb1, s1B, rows, 512, 1);
    gemm_k<64, true><<<(rows + 127) / 128, 128>>>(s1B, sW2, sb2, s2B, rows, HD);
    s3_k<<<(rows + 7) / 8, 256>>>(s2B, sW3, sb3, out, rows);
}